// round 3
// baseline (speedup 1.0000x reference)
#include <cuda_runtime.h>
#include <math.h>

// ---------------- scratch (static device allocations; no cudaMalloc) ----------------
#define S_LEN 2048
#define D_DIM 1024
#define NHEAD 16
#define DH 64
#define POSLEN 512            // 2*SPAN
#define C2P_ELEMS (NHEAD * S_LEN * POSLEN)   // 16.7M

__device__ float g_q[S_LEN * D_DIM];
__device__ float g_k[S_LEN * D_DIM];
__device__ float g_v[S_LEN * D_DIM];
__device__ float g_pk[POSLEN * D_DIM];
__device__ float g_pq[POSLEN * D_DIM];
__device__ float g_c2p[C2P_ELEMS];
__device__ float g_p2c[C2P_ELEMS];

// ---------------- generic NN sgemm with bias: C = A(MxK) @ B(KxN) + bias ----------------
#define GB 64
#define GKT 16
__global__ __launch_bounds__(256) void sgemm_nn_bias(
    const float* __restrict__ A, const float* __restrict__ B,
    const float* __restrict__ bias, float* __restrict__ C,
    int M, int N, int K)
{
    __shared__ float As[GKT][GB + 1];
    __shared__ float Bs[GKT][GB + 1];
    const int tx = threadIdx.x;
    const int m0 = blockIdx.y * GB, n0 = blockIdx.x * GB;
    const int tr = tx >> 4, tc = tx & 15;
    float acc[4][4] = {};
    for (int k0 = 0; k0 < K; k0 += GKT) {
        #pragma unroll
        for (int i = 0; i < 4; i++) {
            int e = tx + i * 256;
            int r = e >> 4, c = e & 15;
            As[c][r] = A[(size_t)(m0 + r) * K + k0 + c];
        }
        #pragma unroll
        for (int i = 0; i < 4; i++) {
            int e = tx + i * 256;
            int r = e >> 6, c = e & 63;
            Bs[r][c] = B[(size_t)(k0 + r) * N + n0 + c];
        }
        __syncthreads();
        #pragma unroll
        for (int kk = 0; kk < GKT; kk++) {
            float a[4], b[4];
            #pragma unroll
            for (int i = 0; i < 4; i++) a[i] = As[kk][tr * 4 + i];
            #pragma unroll
            for (int j = 0; j < 4; j++) b[j] = Bs[kk][tc * 4 + j];
            #pragma unroll
            for (int i = 0; i < 4; i++)
                #pragma unroll
                for (int j = 0; j < 4; j++) acc[i][j] += a[i] * b[j];
        }
        __syncthreads();
    }
    #pragma unroll
    for (int i = 0; i < 4; i++) {
        int m = m0 + tr * 4 + i;
        #pragma unroll
        for (int j = 0; j < 4; j++) {
            int n = n0 + tc * 4 + j;
            C[(size_t)m * N + n] = acc[i][j] + bias[n];
        }
    }
}

// ---------------- per-head NT sgemm: C[h] = A_h (Mx64) @ B_h^T (Nx64) ----------------
// A row m uses cols [h*64, h*64+64) of a row-major (?,1024) matrix; same for B.
// C laid out flat: h * (M*N) + m*N + n   (matches reference .reshape(-1) order)
__global__ __launch_bounds__(256) void sgemm_nt_head(
    const float* __restrict__ A, const float* __restrict__ B, float* __restrict__ C,
    int M, int N)
{
    __shared__ float As[64][65];
    __shared__ float Bs[64][65];
    const int tx = threadIdx.x;
    const int h = blockIdx.z;
    const int m0 = blockIdx.y * 64, n0 = blockIdx.x * 64;
    const int tr = tx >> 4, tc = tx & 15;
    #pragma unroll
    for (int i = 0; i < 16; i++) {
        int e = tx + i * 256;
        int r = e >> 6, c = e & 63;
        As[r][c] = A[(size_t)(m0 + r) * D_DIM + h * DH + c];
    }
    #pragma unroll
    for (int i = 0; i < 16; i++) {
        int e = tx + i * 256;
        int r = e >> 6, c = e & 63;
        Bs[r][c] = B[(size_t)(n0 + r) * D_DIM + h * DH + c];
    }
    __syncthreads();
    float acc[4][4] = {};
    #pragma unroll
    for (int kk = 0; kk < 64; kk++) {
        float a[4], b[4];
        #pragma unroll
        for (int i = 0; i < 4; i++) a[i] = As[tr * 4 + i][kk];
        #pragma unroll
        for (int j = 0; j < 4; j++) b[j] = Bs[tc * 4 + j][kk];
        #pragma unroll
        for (int i = 0; i < 4; i++)
            #pragma unroll
            for (int j = 0; j < 4; j++) acc[i][j] += a[i] * b[j];
    }
    float* Ch = C + (size_t)h * M * N;
    #pragma unroll
    for (int i = 0; i < 4; i++) {
        int m = m0 + tr * 4 + i;
        #pragma unroll
        for (int j = 0; j < 4; j++) {
            int n = n0 + tc * 4 + j;
            Ch[(size_t)m * N + n] = acc[i][j];
        }
    }
}

// ---------------- fused flash attention + disentangled bias gathers ----------------
#define AM 64   // query rows per block
#define AN 32   // key cols per tile
__global__ __launch_bounds__(256) void attn_kernel(
    const float* __restrict__ Q, const float* __restrict__ Km,
    const float* __restrict__ V, const float* __restrict__ c2p,
    const float* __restrict__ p2c, const int* __restrict__ ids,
    const int* __restrict__ ids_t, float* __restrict__ out)
{
    const int h = blockIdx.y;
    const int s0 = blockIdx.x * AM;
    const int tid = threadIdx.x;          // 256 threads
    const int r = tid >> 2;               // 0..63 query row within tile
    const int q4 = tid & 3;               // 4 threads cooperate per row
    const int cbase = q4 * 16;            // 16 output dims owned

    __shared__ float qs[AM][DH + 1];
    __shared__ float ks[AN][DH + 1];
    __shared__ float vs[AN][DH];
    __shared__ float ss[AM][AN + 1];

    const float inv_scale = 0.07216878364870322f;  // 1/sqrt(64*3)

    #pragma unroll
    for (int i = 0; i < 16; i++) {
        int e = tid + i * 256;
        int rr = e >> 6, c = e & 63;
        qs[rr][c] = Q[(size_t)(s0 + rr) * D_DIM + h * DH + c];
    }

    float m = -INFINITY, l = 0.f;
    float o[16];
    #pragma unroll
    for (int i = 0; i < 16; i++) o[i] = 0.f;

    const size_t ids_row_base = ((size_t)h * S_LEN + (s0 + r)) * S_LEN;

    for (int t0 = 0; t0 < S_LEN; t0 += AN) {
        #pragma unroll
        for (int i = 0; i < 8; i++) {
            int e = tid + i * 256;
            int rr = e >> 6, c = e & 63;
            ks[rr][c] = Km[(size_t)(t0 + rr) * D_DIM + h * DH + c];
            vs[rr][c] = V[(size_t)(t0 + rr) * D_DIM + h * DH + c];
        }
        __syncthreads();

        // scores (raw, scaled) for 8 (r, j) pairs per thread
        #pragma unroll
        for (int jj = 0; jj < 8; jj++) {
            int j = q4 + 4 * jj;
            float d = 0.f;
            #pragma unroll
            for (int kk = 0; kk < DH; kk++) d += qs[r][kk] * ks[j][kk];
            int t = t0 + j;
            float b1 = c2p[ids[ids_row_base + t]];
            float b2 = p2c[ids_t[((size_t)h * S_LEN + t) * S_LEN + (s0 + r)]];
            ss[r][j] = (d + b1 + b2) * inv_scale;
        }
        __syncthreads();

        // row max (redundant across the 4 threads of a row; consistent)
        float mt = -INFINITY;
        #pragma unroll
        for (int j = 0; j < AN; j++) mt = fmaxf(mt, ss[r][j]);
        float mn = fmaxf(m, mt);
        float corr = __expf(m - mn);
        __syncthreads();

        // exponentiate own slice in place
        #pragma unroll
        for (int j = q4 * 8; j < q4 * 8 + 8; j++)
            ss[r][j] = __expf(ss[r][j] - mn);
        __syncthreads();

        float ls = 0.f;
        #pragma unroll
        for (int j = 0; j < AN; j++) ls += ss[r][j];
        l = l * corr + ls;
        #pragma unroll
        for (int cc = 0; cc < 16; cc++) o[cc] *= corr;
        #pragma unroll
        for (int j = 0; j < AN; j++) {
            float p = ss[r][j];
            #pragma unroll
            for (int cc = 0; cc < 16; cc++) o[cc] += p * vs[j][cbase + cc];
        }
        m = mn;
        __syncthreads();
    }

    float invl = 1.f / l;
    #pragma unroll
    for (int cc = 0; cc < 16; cc++)
        out[(size_t)(s0 + r) * D_DIM + h * DH + cbase + cc] = o[cc] * invl;
}

// ---------------- host launcher ----------------
extern "C" void kernel_launch(void* const* d_in, const int* in_sizes, int n_in,
                              void* d_out, int out_size)
{
    const float* hidden = (const float*)d_in[0];   // (1,2048,1024)
    const float* rel    = (const float*)d_in[1];   // (512,1024)
    const float* Wq     = (const float*)d_in[2];
    const float* bq     = (const float*)d_in[3];
    const float* Wk     = (const float*)d_in[4];
    const float* bk     = (const float*)d_in[5];
    const float* Wv     = (const float*)d_in[6];
    const float* bv     = (const float*)d_in[7];
    const int*   ids    = (const int*)d_in[8];
    const int*   ids_t  = (const int*)d_in[9];
    float* out = (float*)d_out;

    void *pq, *pk, *pv, *ppk, *ppq, *pc2p, *pp2c;
    cudaGetSymbolAddress(&pq, g_q);
    cudaGetSymbolAddress(&pk, g_k);
    cudaGetSymbolAddress(&pv, g_v);
    cudaGetSymbolAddress(&ppk, g_pk);
    cudaGetSymbolAddress(&ppq, g_pq);
    cudaGetSymbolAddress(&pc2p, g_c2p);
    cudaGetSymbolAddress(&pp2c, g_p2c);
    float* q = (float*)pq;  float* k = (float*)pk;  float* v = (float*)pv;
    float* posk = (float*)ppk; float* posq = (float*)ppq;
    float* c2p = (float*)pc2p; float* p2c = (float*)pp2c;

    // QKV projections: (2048x1024) @ (1024x1024) + bias
    dim3 gq(D_DIM / GB, S_LEN / GB);
    sgemm_nn_bias<<<gq, 256>>>(hidden, Wq, bq, q, S_LEN, D_DIM, D_DIM);
    sgemm_nn_bias<<<gq, 256>>>(hidden, Wk, bk, k, S_LEN, D_DIM, D_DIM);
    sgemm_nn_bias<<<gq, 256>>>(hidden, Wv, bv, v, S_LEN, D_DIM, D_DIM);

    // positional projections: (512x1024) @ (1024x1024) + bias
    dim3 gp(D_DIM / GB, POSLEN / GB);
    sgemm_nn_bias<<<gp, 256>>>(rel, Wk, bk, posk, POSLEN, D_DIM, D_DIM);
    sgemm_nn_bias<<<gp, 256>>>(rel, Wq, bq, posq, POSLEN, D_DIM, D_DIM);

    // c2p[h] = q_h @ posk_h^T ; p2c[h] = k_h @ posq_h^T   (per-head K=64)
    dim3 gc(POSLEN / 64, S_LEN / 64, NHEAD);
    sgemm_nt_head<<<gc, 256>>>(q, posk, c2p, S_LEN, POSLEN);
    sgemm_nt_head<<<gc, 256>>>(k, posq, p2c, S_LEN, POSLEN);

    // fused attention with disentangled-bias gathers + online softmax
    dim3 ga(S_LEN / AM, NHEAD);
    attn_kernel<<<ga, 256>>>(q, k, v, c2p, p2c, ids, ids_t, out);
}

// round 5
// speedup vs baseline: 1.5697x; 1.5697x over previous
#include <cuda_runtime.h>
#include <math.h>

#define S_LEN 2048
#define D_DIM 1024
#define NHEAD 16
#define DH 64
#define POSLEN 512
#define C2P_ELEMS (NHEAD * S_LEN * POSLEN)

__device__ float g_q[S_LEN * D_DIM];
__device__ float g_k[S_LEN * D_DIM];
__device__ float g_v[S_LEN * D_DIM];
__device__ float g_pk[POSLEN * D_DIM];
__device__ float g_pq[POSLEN * D_DIM];
__device__ float g_c2p[C2P_ELEMS];
__device__ float g_p2c[C2P_ELEMS];

// ================= projection GEMM: C_z = A(Mx1024) @ W_z(1024x1024) + b_z =================
// 128x128 tile, 256 threads, 8x8 micro-tile, k-tile 16.
__global__ __launch_bounds__(256) void gemm_proj(
    const float* __restrict__ A,
    const float* __restrict__ W0, const float* __restrict__ W1, const float* __restrict__ W2,
    const float* __restrict__ b0, const float* __restrict__ b1, const float* __restrict__ b2,
    float* __restrict__ C0, float* __restrict__ C1, float* __restrict__ C2)
{
    const float* W; const float* bias; float* C;
    if (blockIdx.z == 0)      { W = W0; bias = b0; C = C0; }
    else if (blockIdx.z == 1) { W = W1; bias = b1; C = C1; }
    else                      { W = W2; bias = b2; C = C2; }

    __shared__ float As[16][132];   // transposed: As[k][m]
    __shared__ float Bs[16][132];   // Bs[k][n]

    const int tid = threadIdx.x;
    const int tr = tid >> 4, tc = tid & 15;
    const int m0 = blockIdx.y * 128, n0 = blockIdx.x * 128;

    float acc[8][8] = {};

    for (int k0 = 0; k0 < 1024; k0 += 16) {
        #pragma unroll
        for (int u = 0; u < 2; u++) {
            int idx = tid + u * 256;           // 512 float4 = 128 rows x 4
            int r = idx >> 2, c4 = idx & 3;
            float4 av = *(const float4*)(A + (size_t)(m0 + r) * 1024 + k0 + c4 * 4);
            As[c4 * 4 + 0][r] = av.x; As[c4 * 4 + 1][r] = av.y;
            As[c4 * 4 + 2][r] = av.z; As[c4 * 4 + 3][r] = av.w;
        }
        #pragma unroll
        for (int u = 0; u < 2; u++) {
            int idx = tid + u * 256;           // 512 float4 = 16 rows x 32
            int r = idx >> 5, c4 = idx & 31;
            float4 bv = *(const float4*)(W + (size_t)(k0 + r) * 1024 + n0 + c4 * 4);
            *(float4*)(&Bs[r][c4 * 4]) = bv;
        }
        __syncthreads();
        #pragma unroll
        for (int kk = 0; kk < 16; kk++) {
            float a[8], b[8];
            *(float4*)(a)     = *(const float4*)(&As[kk][tr * 8]);
            *(float4*)(a + 4) = *(const float4*)(&As[kk][tr * 8 + 4]);
            *(float4*)(b)     = *(const float4*)(&Bs[kk][tc * 8]);
            *(float4*)(b + 4) = *(const float4*)(&Bs[kk][tc * 8 + 4]);
            #pragma unroll
            for (int i = 0; i < 8; i++)
                #pragma unroll
                for (int j = 0; j < 8; j++)
                    acc[i][j] += a[i] * b[j];
        }
        __syncthreads();
    }

    #pragma unroll
    for (int i = 0; i < 8; i++) {
        int m = m0 + tr * 8 + i;
        #pragma unroll
        for (int j = 0; j < 8; j++) {
            int n = n0 + tc * 8 + j;
            acc[i][j] += bias[n];
        }
        *(float4*)(C + (size_t)m * 1024 + n0 + tc * 8)     = *(float4*)(&acc[i][0]);
        *(float4*)(C + (size_t)m * 1024 + n0 + tc * 8 + 4) = *(float4*)(&acc[i][4]);
    }
}

// ================= per-head NT GEMM: C[h] = A_h(Mx64) @ B_h^T(Nx64), K=64 =================
// 128x128 tile, 8x8 micro-tile. A,B rows use cols [h*64, h*64+64) of row-major (?,1024).
__global__ __launch_bounds__(256) void gemm_rel(
    const float* __restrict__ A, const float* __restrict__ B, float* __restrict__ C,
    int M, int N)
{
    __shared__ float As[16][132];
    __shared__ float Bs[16][132];

    const int tid = threadIdx.x;
    const int tr = tid >> 4, tc = tid & 15;
    const int h = blockIdx.z;
    const int hb = h * DH;
    const int m0 = blockIdx.y * 128, n0 = blockIdx.x * 128;

    float acc[8][8] = {};

    for (int k0 = 0; k0 < 64; k0 += 16) {
        #pragma unroll
        for (int u = 0; u < 2; u++) {
            int idx = tid + u * 256;
            int r = idx >> 2, c4 = idx & 3;
            float4 av = *(const float4*)(A + (size_t)(m0 + r) * 1024 + hb + k0 + c4 * 4);
            As[c4 * 4 + 0][r] = av.x; As[c4 * 4 + 1][r] = av.y;
            As[c4 * 4 + 2][r] = av.z; As[c4 * 4 + 3][r] = av.w;
        }
        #pragma unroll
        for (int u = 0; u < 2; u++) {
            int idx = tid + u * 256;
            int r = idx >> 2, c4 = idx & 3;
            float4 bv = *(const float4*)(B + (size_t)(n0 + r) * 1024 + hb + k0 + c4 * 4);
            Bs[c4 * 4 + 0][r] = bv.x; Bs[c4 * 4 + 1][r] = bv.y;
            Bs[c4 * 4 + 2][r] = bv.z; Bs[c4 * 4 + 3][r] = bv.w;
        }
        __syncthreads();
        #pragma unroll
        for (int kk = 0; kk < 16; kk++) {
            float a[8], b[8];
            *(float4*)(a)     = *(const float4*)(&As[kk][tr * 8]);
            *(float4*)(a + 4) = *(const float4*)(&As[kk][tr * 8 + 4]);
            *(float4*)(b)     = *(const float4*)(&Bs[kk][tc * 8]);
            *(float4*)(b + 4) = *(const float4*)(&Bs[kk][tc * 8 + 4]);
            #pragma unroll
            for (int i = 0; i < 8; i++)
                #pragma unroll
                for (int j = 0; j < 8; j++)
                    acc[i][j] += a[i] * b[j];
        }
        __syncthreads();
    }

    float* Ch = C + (size_t)h * M * N;
    #pragma unroll
    for (int i = 0; i < 8; i++) {
        int m = m0 + tr * 8 + i;
        *(float4*)(Ch + (size_t)m * N + n0 + tc * 8)     = *(float4*)(&acc[i][0]);
        *(float4*)(Ch + (size_t)m * N + n0 + tc * 8 + 4) = *(float4*)(&acc[i][4]);
    }
}

// ================= fused flash attention + disentangled bias gathers =================
// 64 q-rows x 64 k-cols tiles, 256 threads as 16x16, 4x4 micro-tile, all LDS vectorized.
#define ATT_SMEM_FLOATS (3 * 64 * 68 + 64 * 64 + 3 * 64)
__global__ __launch_bounds__(256, 2) void attn2(
    const float* __restrict__ Q, const float* __restrict__ Km,
    const float* __restrict__ V, const float* __restrict__ c2p,
    const float* __restrict__ p2c, const int* __restrict__ ids,
    const int* __restrict__ ids_t, float* __restrict__ out)
{
    extern __shared__ float sm[];
    float* qsT  = sm;                    // [64 kk][68] rows-in-cols
    float* ksT  = qsT + 64 * 68;         // [64 kk][68]
    float* ssT  = ksT + 64 * 68;         // [64 col][68] scores, col-major
    float* vs   = ssT + 64 * 68;         // [64 j][64 dim]
    float* rowm = vs + 64 * 64;
    float* rowl = rowm + 64;
    float* rowc = rowl + 64;

    const int h  = blockIdx.y;
    const int s0 = blockIdx.x * 64;
    const int hb = h * DH;
    const int tid = threadIdx.x;
    const int ty = tid >> 4, tx = tid & 15;   // thread owns rows ty*4+i, cols tx*4+jj

    const float inv_scale = 0.07216878364870322f;  // 1/sqrt(64*3)

    // load Q tile transposed: qsT[c][r] = Q[s0+r][hb+c]
    #pragma unroll
    for (int u = 0; u < 4; u++) {
        int idx = tid + u * 256;           // 1024 float4
        int c4 = idx >> 6, r = idx & 63;
        float4 qv = *(const float4*)(Q + (size_t)(s0 + r) * 1024 + hb + c4 * 4);
        qsT[(c4 * 4 + 0) * 68 + r] = qv.x; qsT[(c4 * 4 + 1) * 68 + r] = qv.y;
        qsT[(c4 * 4 + 2) * 68 + r] = qv.z; qsT[(c4 * 4 + 3) * 68 + r] = qv.w;
    }
    if (tid < 64) { rowm[tid] = -INFINITY; rowl[tid] = 0.f; }

    float o[4][4] = {};

    for (int t0 = 0; t0 < S_LEN; t0 += 64) {
        // load K tile transposed + V tile direct
        #pragma unroll
        for (int u = 0; u < 4; u++) {
            int idx = tid + u * 256;
            int c4 = idx >> 6, r = idx & 63;
            float4 kv = *(const float4*)(Km + (size_t)(t0 + r) * 1024 + hb + c4 * 4);
            ksT[(c4 * 4 + 0) * 68 + r] = kv.x; ksT[(c4 * 4 + 1) * 68 + r] = kv.y;
            ksT[(c4 * 4 + 2) * 68 + r] = kv.z; ksT[(c4 * 4 + 3) * 68 + r] = kv.w;
        }
        #pragma unroll
        for (int u = 0; u < 4; u++) {
            int idx = tid + u * 256;
            int r = idx >> 4, c4 = idx & 15;
            float4 vv = *(const float4*)(V + (size_t)(t0 + r) * 1024 + hb + c4 * 4);
            *(float4*)(&vs[r * 64 + c4 * 4]) = vv;
        }
        __syncthreads();

        // QK^T 4x4 micro-tile
        float acc[4][4] = {};
        #pragma unroll 8
        for (int kk = 0; kk < 64; kk++) {
            float a[4], b[4];
            *(float4*)a = *(const float4*)(qsT + kk * 68 + ty * 4);
            *(float4*)b = *(const float4*)(ksT + kk * 68 + tx * 4);
            #pragma unroll
            for (int i = 0; i < 4; i++)
                #pragma unroll
                for (int jj = 0; jj < 4; jj++)
                    acc[i][jj] += a[i] * b[jj];
        }

        // c2p bias: row-major int4 index loads, then random gathers
        #pragma unroll
        for (int i = 0; i < 4; i++) {
            int4 iv = *(const int4*)(ids + (((size_t)h * S_LEN + s0 + ty * 4 + i) << 11) + t0 + tx * 4);
            acc[i][0] += c2p[iv.x]; acc[i][1] += c2p[iv.y];
            acc[i][2] += c2p[iv.z]; acc[i][3] += c2p[iv.w];
        }
        // p2c bias: transposed index layout -> int4 along rows
        #pragma unroll
        for (int jj = 0; jj < 4; jj++) {
            int4 iv = *(const int4*)(ids_t + (((size_t)h * S_LEN + t0 + tx * 4 + jj) << 11) + s0 + ty * 4);
            acc[0][jj] += p2c[iv.x]; acc[1][jj] += p2c[iv.y];
            acc[2][jj] += p2c[iv.z]; acc[3][jj] += p2c[iv.w];
        }

        // store scaled scores col-major: ssT[col][row]
        #pragma unroll
        for (int jj = 0; jj < 4; jj++) {
            float4 s4;
            s4.x = acc[0][jj] * inv_scale; s4.y = acc[1][jj] * inv_scale;
            s4.z = acc[2][jj] * inv_scale; s4.w = acc[3][jj] * inv_scale;
            *(float4*)(ssT + (tx * 4 + jj) * 68 + ty * 4) = s4;
        }
        __syncthreads();

        // online-softmax row stats (threads 0..63, one row each; conflict-free scans)
        if (tid < 64) {
            int r = tid;
            float mt = -INFINITY;
            #pragma unroll 8
            for (int j = 0; j < 64; j++) mt = fmaxf(mt, ssT[j * 68 + r]);
            float mo = rowm[r];
            float mn = fmaxf(mo, mt);
            float corr = __expf(mo - mn);
            float ls = 0.f;
            #pragma unroll 8
            for (int j = 0; j < 64; j++) {
                float p = __expf(ssT[j * 68 + r] - mn);
                ssT[j * 68 + r] = p;
                ls += p;
            }
            rowl[r] = rowl[r] * corr + ls;
            rowm[r] = mn;
            rowc[r] = corr;
        }
        __syncthreads();

        // rescale accumulators and PV 4x4 micro-tile
        float4 cr = *(const float4*)(rowc + ty * 4);
        float crr[4] = {cr.x, cr.y, cr.z, cr.w};
        #pragma unroll
        for (int i = 0; i < 4; i++)
            #pragma unroll
            for (int jj = 0; jj < 4; jj++)
                o[i][jj] *= crr[i];
        #pragma unroll 8
        for (int j = 0; j < 64; j++) {
            float p[4], vv[4];
            *(float4*)p  = *(const float4*)(ssT + j * 68 + ty * 4);
            *(float4*)vv = *(const float4*)(vs + j * 64 + tx * 4);
            #pragma unroll
            for (int i = 0; i < 4; i++)
                #pragma unroll
                for (int jj = 0; jj < 4; jj++)
                    o[i][jj] += p[i] * vv[jj];
        }
        __syncthreads();
    }

    float4 lv = *(const float4*)(rowl + ty * 4);
    float invl[4] = {1.f / lv.x, 1.f / lv.y, 1.f / lv.z, 1.f / lv.w};
    #pragma unroll
    for (int i = 0; i < 4; i++) {
        float4 ov;
        ov.x = o[i][0] * invl[i]; ov.y = o[i][1] * invl[i];
        ov.z = o[i][2] * invl[i]; ov.w = o[i][3] * invl[i];
        *(float4*)(out + (size_t)(s0 + ty * 4 + i) * 1024 + hb + tx * 4) = ov;
    }
}

// ================= host launcher =================
extern "C" void kernel_launch(void* const* d_in, const int* in_sizes, int n_in,
                              void* d_out, int out_size)
{
    const float* hidden = (const float*)d_in[0];
    const float* rel    = (const float*)d_in[1];
    const float* Wq     = (const float*)d_in[2];
    const float* bq     = (const float*)d_in[3];
    const float* Wk     = (const float*)d_in[4];
    const float* bk     = (const float*)d_in[5];
    const float* Wv     = (const float*)d_in[6];
    const float* bv     = (const float*)d_in[7];
    const int*   ids    = (const int*)d_in[8];
    const int*   ids_t  = (const int*)d_in[9];
    float* out = (float*)d_out;

    void *pq, *pk, *pv, *ppk, *ppq, *pc2p, *pp2c;
    cudaGetSymbolAddress(&pq, g_q);
    cudaGetSymbolAddress(&pk, g_k);
    cudaGetSymbolAddress(&pv, g_v);
    cudaGetSymbolAddress(&ppk, g_pk);
    cudaGetSymbolAddress(&ppq, g_pq);
    cudaGetSymbolAddress(&pc2p, g_c2p);
    cudaGetSymbolAddress(&pp2c, g_p2c);
    float* q = (float*)pq;  float* k = (float*)pk;  float* v = (float*)pv;
    float* posk = (float*)ppk; float* posq = (float*)ppq;
    float* c2p = (float*)pc2p; float* p2c = (float*)pp2c;

    static int smem_set = 0;
    if (!smem_set) {
        cudaFuncSetAttribute(attn2, cudaFuncAttributeMaxDynamicSharedMemorySize,
                             ATT_SMEM_FLOATS * 4);
        smem_set = 1;
    }

    // QKV projections fused in one launch (z selects W/bias/output)
    dim3 gq(1024 / 128, S_LEN / 128, 3);
    gemm_proj<<<gq, 256>>>(hidden, Wq, Wk, Wv, bq, bk, bv, q, k, v);

    // positional projections: posk = rel@Wk+bk, posq = rel@Wq+bq (z=0,1)
    dim3 gp(1024 / 128, POSLEN / 128, 2);
    gemm_proj<<<gp, 256>>>(rel, Wk, Wq, Wq, bk, bq, bq, posk, posq, posq);

    // c2p[h] = q_h @ posk_h^T ; p2c[h] = k_h @ posq_h^T
    dim3 gc(POSLEN / 128, S_LEN / 128, NHEAD);
    gemm_rel<<<gc, 256>>>(q, posk, c2p, S_LEN, POSLEN);
    gemm_rel<<<gc, 256>>>(k, posq, p2c, S_LEN, POSLEN);

    // fused attention
    dim3 ga(S_LEN / 64, NHEAD);
    attn2<<<ga, 256, ATT_SMEM_FLOATS * 4>>>(q, k, v, c2p, p2c, ids, ids_t, out);
}

// round 6
// speedup vs baseline: 1.8970x; 1.2085x over previous
#include <cuda_runtime.h>
#include <cuda_fp16.h>
#include <math.h>

#define S_LEN 2048
#define D_DIM 1024
#define NHEAD 16
#define DH 64
#define POSLEN 512
#define C2P_ELEMS (NHEAD * S_LEN * POSLEN)

__device__ float g_q[S_LEN * D_DIM];
__device__ float g_k[S_LEN * D_DIM];
__device__ float g_v[S_LEN * D_DIM];
__device__ float g_pk[POSLEN * D_DIM];
__device__ float g_pq[POSLEN * D_DIM];
__device__ __half g_c2p_h[C2P_ELEMS];
__device__ __half g_p2c_h[C2P_ELEMS];

// ================= projection GEMM: C_z = A(Mx1024) @ W_z(1024x1024) + b_z =================
__global__ __launch_bounds__(256) void gemm_proj(
    const float* __restrict__ A,
    const float* __restrict__ W0, const float* __restrict__ W1, const float* __restrict__ W2,
    const float* __restrict__ b0, const float* __restrict__ b1, const float* __restrict__ b2,
    float* __restrict__ C0, float* __restrict__ C1, float* __restrict__ C2)
{
    const float* W; const float* bias; float* C;
    if (blockIdx.z == 0)      { W = W0; bias = b0; C = C0; }
    else if (blockIdx.z == 1) { W = W1; bias = b1; C = C1; }
    else                      { W = W2; bias = b2; C = C2; }

    __shared__ float As[16][132];
    __shared__ float Bs[16][132];

    const int tid = threadIdx.x;
    const int tr = tid >> 4, tc = tid & 15;
    const int m0 = blockIdx.y * 128, n0 = blockIdx.x * 128;

    float acc[8][8] = {};

    for (int k0 = 0; k0 < 1024; k0 += 16) {
        #pragma unroll
        for (int u = 0; u < 2; u++) {
            int idx = tid + u * 256;
            int r = idx >> 2, c4 = idx & 3;
            float4 av = *(const float4*)(A + (size_t)(m0 + r) * 1024 + k0 + c4 * 4);
            As[c4 * 4 + 0][r] = av.x; As[c4 * 4 + 1][r] = av.y;
            As[c4 * 4 + 2][r] = av.z; As[c4 * 4 + 3][r] = av.w;
        }
        #pragma unroll
        for (int u = 0; u < 2; u++) {
            int idx = tid + u * 256;
            int r = idx >> 5, c4 = idx & 31;
            float4 bv = *(const float4*)(W + (size_t)(k0 + r) * 1024 + n0 + c4 * 4);
            *(float4*)(&Bs[r][c4 * 4]) = bv;
        }
        __syncthreads();
        #pragma unroll
        for (int kk = 0; kk < 16; kk++) {
            float a[8], b[8];
            *(float4*)(a)     = *(const float4*)(&As[kk][tr * 8]);
            *(float4*)(a + 4) = *(const float4*)(&As[kk][tr * 8 + 4]);
            *(float4*)(b)     = *(const float4*)(&Bs[kk][tc * 8]);
            *(float4*)(b + 4) = *(const float4*)(&Bs[kk][tc * 8 + 4]);
            #pragma unroll
            for (int i = 0; i < 8; i++)
                #pragma unroll
                for (int j = 0; j < 8; j++)
                    acc[i][j] += a[i] * b[j];
        }
        __syncthreads();
    }

    #pragma unroll
    for (int i = 0; i < 8; i++) {
        int m = m0 + tr * 8 + i;
        #pragma unroll
        for (int j = 0; j < 8; j++) {
            int n = n0 + tc * 8 + j;
            acc[i][j] += bias[n];
        }
        *(float4*)(C + (size_t)m * 1024 + n0 + tc * 8)     = *(float4*)(&acc[i][0]);
        *(float4*)(C + (size_t)m * 1024 + n0 + tc * 8 + 4) = *(float4*)(&acc[i][4]);
    }
}

// ================= per-head NT GEMM -> fp16 table: C[h] = A_h(Mx64) @ B_h^T(Nx64) =================
__global__ __launch_bounds__(256) void gemm_rel(
    const float* __restrict__ A, const float* __restrict__ B, __half* __restrict__ C,
    int M, int N)
{
    __shared__ float As[16][132];
    __shared__ float Bs[16][132];

    const int tid = threadIdx.x;
    const int tr = tid >> 4, tc = tid & 15;
    const int h = blockIdx.z;
    const int hb = h * DH;
    const int m0 = blockIdx.y * 128, n0 = blockIdx.x * 128;

    float acc[8][8] = {};

    for (int k0 = 0; k0 < 64; k0 += 16) {
        #pragma unroll
        for (int u = 0; u < 2; u++) {
            int idx = tid + u * 256;
            int r = idx >> 2, c4 = idx & 3;
            float4 av = *(const float4*)(A + (size_t)(m0 + r) * 1024 + hb + k0 + c4 * 4);
            As[c4 * 4 + 0][r] = av.x; As[c4 * 4 + 1][r] = av.y;
            As[c4 * 4 + 2][r] = av.z; As[c4 * 4 + 3][r] = av.w;
        }
        #pragma unroll
        for (int u = 0; u < 2; u++) {
            int idx = tid + u * 256;
            int r = idx >> 2, c4 = idx & 3;
            float4 bv = *(const float4*)(B + (size_t)(n0 + r) * 1024 + hb + k0 + c4 * 4);
            Bs[c4 * 4 + 0][r] = bv.x; Bs[c4 * 4 + 1][r] = bv.y;
            Bs[c4 * 4 + 2][r] = bv.z; Bs[c4 * 4 + 3][r] = bv.w;
        }
        __syncthreads();
        #pragma unroll
        for (int kk = 0; kk < 16; kk++) {
            float a[8], b[8];
            *(float4*)(a)     = *(const float4*)(&As[kk][tr * 8]);
            *(float4*)(a + 4) = *(const float4*)(&As[kk][tr * 8 + 4]);
            *(float4*)(b)     = *(const float4*)(&Bs[kk][tc * 8]);
            *(float4*)(b + 4) = *(const float4*)(&Bs[kk][tc * 8 + 4]);
            #pragma unroll
            for (int i = 0; i < 8; i++)
                #pragma unroll
                for (int j = 0; j < 8; j++)
                    acc[i][j] += a[i] * b[j];
        }
        __syncthreads();
    }

    __half* Ch = C + (size_t)h * M * N;
    #pragma unroll
    for (int i = 0; i < 8; i++) {
        int m = m0 + tr * 8 + i;
        __half2 h4[4];
        #pragma unroll
        for (int p = 0; p < 4; p++)
            h4[p] = __floats2half2_rn(acc[i][2 * p], acc[i][2 * p + 1]);
        *(int4*)(Ch + (size_t)m * N + n0 + tc * 8) = *(int4*)h4;
    }
}

// ================= fused flash attention + disentangled bias gathers =================
// 64x64 tiles, 256 threads (16x16), 4x4 micro-tile, shuffle softmax, hoisted gathers.
#define ATT_SMEM_FLOATS (3 * 64 * 68 + 64 * 64)

__device__ __forceinline__ float rmax16(float v) {
    #pragma unroll
    for (int off = 8; off; off >>= 1)
        v = fmaxf(v, __shfl_xor_sync(0xffffffffu, v, off));
    return v;
}
__device__ __forceinline__ float rsum16(float v) {
    #pragma unroll
    for (int off = 8; off; off >>= 1)
        v += __shfl_xor_sync(0xffffffffu, v, off);
    return v;
}

__global__ __launch_bounds__(256, 2) void attn2(
    const float* __restrict__ Q, const float* __restrict__ Km,
    const float* __restrict__ V, const __half* __restrict__ c2p,
    const __half* __restrict__ p2c, const int* __restrict__ ids,
    const int* __restrict__ ids_t, float* __restrict__ out)
{
    extern __shared__ float sm[];
    float* qsT = sm;               // [64 kk][68]
    float* ksT = qsT + 64 * 68;    // [64 kk][68]
    float* ssT = ksT + 64 * 68;    // [64 col][68] probs, col-major
    float* vs  = ssT + 64 * 68;    // [64 j][64 dim]

    const int h  = blockIdx.y;
    const int s0 = blockIdx.x * 64;
    const int hb = h * DH;
    const int tid = threadIdx.x;
    const int ty = tid >> 4, tx = tid & 15;

    const float inv_scale = 0.07216878364870322f;  // 1/sqrt(64*3)

    // load Q tile transposed
    #pragma unroll
    for (int u = 0; u < 4; u++) {
        int idx = tid + u * 256;
        int c4 = idx >> 6, r = idx & 63;
        float4 qv = *(const float4*)(Q + (size_t)(s0 + r) * 1024 + hb + c4 * 4);
        qsT[(c4 * 4 + 0) * 68 + r] = qv.x; qsT[(c4 * 4 + 1) * 68 + r] = qv.y;
        qsT[(c4 * 4 + 2) * 68 + r] = qv.z; qsT[(c4 * 4 + 3) * 68 + r] = qv.w;
    }

    float m_run[4], l_run[4];
    #pragma unroll
    for (int i = 0; i < 4; i++) { m_run[i] = -INFINITY; l_run[i] = 0.f; }
    float o[4][4] = {};

    for (int t0 = 0; t0 < S_LEN; t0 += 64) {
        // ---- issue bias index loads + gathers FIRST (hidden under K/V load + QK) ----
        float bc[4][4], bp[4][4];
        {
            int4 ivr[4], ivc[4];
            #pragma unroll
            for (int i = 0; i < 4; i++)
                ivr[i] = *(const int4*)(ids + (((size_t)h * S_LEN + s0 + ty * 4 + i) << 11) + t0 + tx * 4);
            #pragma unroll
            for (int jj = 0; jj < 4; jj++)
                ivc[jj] = *(const int4*)(ids_t + (((size_t)h * S_LEN + t0 + tx * 4 + jj) << 11) + s0 + ty * 4);
            #pragma unroll
            for (int i = 0; i < 4; i++) {
                bc[i][0] = __half2float(c2p[ivr[i].x]);
                bc[i][1] = __half2float(c2p[ivr[i].y]);
                bc[i][2] = __half2float(c2p[ivr[i].z]);
                bc[i][3] = __half2float(c2p[ivr[i].w]);
            }
            #pragma unroll
            for (int jj = 0; jj < 4; jj++) {
                bp[0][jj] = __half2float(p2c[ivc[jj].x]);
                bp[1][jj] = __half2float(p2c[ivc[jj].y]);
                bp[2][jj] = __half2float(p2c[ivc[jj].z]);
                bp[3][jj] = __half2float(p2c[ivc[jj].w]);
            }
        }

        // ---- load K tile transposed + V tile ----
        #pragma unroll
        for (int u = 0; u < 4; u++) {
            int idx = tid + u * 256;
            int c4 = idx >> 6, r = idx & 63;
            float4 kv = *(const float4*)(Km + (size_t)(t0 + r) * 1024 + hb + c4 * 4);
            ksT[(c4 * 4 + 0) * 68 + r] = kv.x; ksT[(c4 * 4 + 1) * 68 + r] = kv.y;
            ksT[(c4 * 4 + 2) * 68 + r] = kv.z; ksT[(c4 * 4 + 3) * 68 + r] = kv.w;
        }
        #pragma unroll
        for (int u = 0; u < 4; u++) {
            int idx = tid + u * 256;
            int r = idx >> 4, c4 = idx & 15;
            float4 vv = *(const float4*)(V + (size_t)(t0 + r) * 1024 + hb + c4 * 4);
            *(float4*)(&vs[r * 64 + c4 * 4]) = vv;
        }
        __syncthreads();

        // ---- QK^T 4x4 micro-tile ----
        float acc[4][4] = {};
        #pragma unroll 8
        for (int kk = 0; kk < 64; kk++) {
            float a[4], b[4];
            *(float4*)a = *(const float4*)(qsT + kk * 68 + ty * 4);
            *(float4*)b = *(const float4*)(ksT + kk * 68 + tx * 4);
            #pragma unroll
            for (int i = 0; i < 4; i++)
                #pragma unroll
                for (int jj = 0; jj < 4; jj++)
                    acc[i][jj] += a[i] * b[jj];
        }

        // ---- add biases, scale ----
        #pragma unroll
        for (int i = 0; i < 4; i++)
            #pragma unroll
            for (int jj = 0; jj < 4; jj++)
                acc[i][jj] = (acc[i][jj] + bc[i][jj] + bp[i][jj]) * inv_scale;

        // ---- online softmax, fully parallel via 16-lane shuffles ----
        #pragma unroll
        for (int i = 0; i < 4; i++) {
            float mt = fmaxf(fmaxf(acc[i][0], acc[i][1]), fmaxf(acc[i][2], acc[i][3]));
            mt = rmax16(mt);
            float mn = fmaxf(m_run[i], mt);
            float corr = __expf(m_run[i] - mn);
            m_run[i] = mn;
            float ls = 0.f;
            #pragma unroll
            for (int jj = 0; jj < 4; jj++) {
                acc[i][jj] = __expf(acc[i][jj] - mn);
                ls += acc[i][jj];
            }
            ls = rsum16(ls);
            l_run[i] = l_run[i] * corr + ls;
            #pragma unroll
            for (int jj = 0; jj < 4; jj++) o[i][jj] *= corr;
        }

        // ---- exchange probs through smem (col-major for vectorized PV reads) ----
        #pragma unroll
        for (int jj = 0; jj < 4; jj++) {
            float4 s4;
            s4.x = acc[0][jj]; s4.y = acc[1][jj]; s4.z = acc[2][jj]; s4.w = acc[3][jj];
            *(float4*)(ssT + (tx * 4 + jj) * 68 + ty * 4) = s4;
        }
        __syncthreads();

        // ---- PV 4x4 micro-tile ----
        #pragma unroll 8
        for (int j = 0; j < 64; j++) {
            float p[4], vv[4];
            *(float4*)p  = *(const float4*)(ssT + j * 68 + ty * 4);
            *(float4*)vv = *(const float4*)(vs + j * 64 + tx * 4);
            #pragma unroll
            for (int i = 0; i < 4; i++)
                #pragma unroll
                for (int jj = 0; jj < 4; jj++)
                    o[i][jj] += p[i] * vv[jj];
        }
        __syncthreads();
    }

    #pragma unroll
    for (int i = 0; i < 4; i++) {
        float invl = 1.f / l_run[i];
        float4 ov;
        ov.x = o[i][0] * invl; ov.y = o[i][1] * invl;
        ov.z = o[i][2] * invl; ov.w = o[i][3] * invl;
        *(float4*)(out + (size_t)(s0 + ty * 4 + i) * 1024 + hb + tx * 4) = ov;
    }
}

// ================= host launcher =================
extern "C" void kernel_launch(void* const* d_in, const int* in_sizes, int n_in,
                              void* d_out, int out_size)
{
    const float* hidden = (const float*)d_in[0];
    const float* rel    = (const float*)d_in[1];
    const float* Wq     = (const float*)d_in[2];
    const float* bq     = (const float*)d_in[3];
    const float* Wk     = (const float*)d_in[4];
    const float* bk     = (const float*)d_in[5];
    const float* Wv     = (const float*)d_in[6];
    const float* bv     = (const float*)d_in[7];
    const int*   ids    = (const int*)d_in[8];
    const int*   ids_t  = (const int*)d_in[9];
    float* out = (float*)d_out;

    void *pq, *pk, *pv, *ppk, *ppq, *pc2p, *pp2c;
    cudaGetSymbolAddress(&pq, g_q);
    cudaGetSymbolAddress(&pk, g_k);
    cudaGetSymbolAddress(&pv, g_v);
    cudaGetSymbolAddress(&ppk, g_pk);
    cudaGetSymbolAddress(&ppq, g_pq);
    cudaGetSymbolAddress(&pc2p, g_c2p_h);
    cudaGetSymbolAddress(&pp2c, g_p2c_h);
    float* q = (float*)pq;  float* k = (float*)pk;  float* v = (float*)pv;
    float* posk = (float*)ppk; float* posq = (float*)ppq;
    __half* c2p = (__half*)pc2p; __half* p2c = (__half*)pp2c;

    static int smem_set = 0;
    if (!smem_set) {
        cudaFuncSetAttribute(attn2, cudaFuncAttributeMaxDynamicSharedMemorySize,
                             ATT_SMEM_FLOATS * 4);
        smem_set = 1;
    }

    dim3 gq(1024 / 128, S_LEN / 128, 3);
    gemm_proj<<<gq, 256>>>(hidden, Wq, Wk, Wv, bq, bk, bv, q, k, v);

    dim3 gp(1024 / 128, POSLEN / 128, 2);
    gemm_proj<<<gp, 256>>>(rel, Wk, Wq, Wq, bk, bq, bq, posk, posq, posq);

    dim3 gc(POSLEN / 128, S_LEN / 128, NHEAD);
    gemm_rel<<<gc, 256>>>(q, posk, c2p, S_LEN, POSLEN);
    gemm_rel<<<gc, 256>>>(k, posq, p2c, S_LEN, POSLEN);

    dim3 ga(S_LEN / 64, NHEAD);
    attn2<<<ga, 256, ATT_SMEM_FLOATS * 4>>>(q, k, v, c2p, p2c, ids, ids_t, out);
}